// round 1
// baseline (speedup 1.0000x reference)
#include <cuda_runtime.h>
#include <math.h>

#define NHEADS 16
#define HD 64
#define DM 1024
#define PDIM 64
#define MAXS 2048
#define MAXB 2

// scratch (device globals — no runtime allocation)
__device__ float g_masses[MAXB * NHEADS * MAXS];              // [B,H,S]
__device__ float g_invd[(size_t)MAXS * MAXS];                 // 1 / dist_sq_mod
__device__ float g_O[(size_t)MAXB * MAXS * DM];               // attention output

// ---------------------------------------------------------------------------
// Kernel 1: masses[b,h,s] = softplus( dot(xh[b,s,h,:], W_mass[h,:]) )
// one warp per (b,h,s)
// ---------------------------------------------------------------------------
__global__ void mass_kernel(const float* __restrict__ x,
                            const float* __restrict__ Wm, int S) {
    int gw   = (blockIdx.x * 256 + threadIdx.x) >> 5;
    int lane = threadIdx.x & 31;
    int s = gw % S;
    int h = (gw / S) & (NHEADS - 1);
    int b = gw / (S * NHEADS);
    const float* xr = x + ((size_t)(b * S + s)) * DM + h * HD;
    float t = xr[lane] * Wm[h * HD + lane] + xr[lane + 32] * Wm[h * HD + lane + 32];
#pragma unroll
    for (int o = 16; o; o >>= 1) t += __shfl_xor_sync(0xffffffffu, t, o);
    if (lane == 0) {
        float m = (t > 20.f) ? t : log1pf(expf(t));
        g_masses[(b * NHEADS + h) * S + s] = m;
    }
}

// ---------------------------------------------------------------------------
// Kernel 2: g_invd[i,j] = 1 / max( d2 * (1 + 0.15*cos(sqrt(d2+1e-6))), 1e-6 )
// 64x64 output tile per block, direct (a-b)^2 accumulation (exact diagonal 0)
// ---------------------------------------------------------------------------
__global__ void dist_kernel(const float* __restrict__ pos, int S) {
    __shared__ float Pi[PDIM][65];   // [p][row]
    __shared__ float Pj[PDIM][65];
    int i0 = blockIdx.x * 64, j0 = blockIdx.y * 64;
    int tid = threadIdx.x;
#pragma unroll
    for (int v = 0; v < 16; v++) {
        int e = v * 256 + tid;
        int r = e >> 6, p = e & 63;
        Pi[p][r] = pos[(size_t)(i0 + r) * PDIM + p];
        Pj[p][r] = pos[(size_t)(j0 + r) * PDIM + p];
    }
    __syncthreads();
    int ty = tid >> 4, tx = tid & 15;
    float acc[4][4] = {};
#pragma unroll
    for (int p = 0; p < PDIM; p++) {
        float a[4], bb[4];
#pragma unroll
        for (int i = 0; i < 4; i++) a[i] = Pi[p][ty * 4 + i];
#pragma unroll
        for (int j = 0; j < 4; j++) bb[j] = Pj[p][tx * 4 + j];
#pragma unroll
        for (int i = 0; i < 4; i++)
#pragma unroll
            for (int j = 0; j < 4; j++) {
                float d = a[i] - bb[j];
                acc[i][j] = fmaf(d, d, acc[i][j]);
            }
    }
#pragma unroll
    for (int i = 0; i < 4; i++)
#pragma unroll
        for (int j = 0; j < 4; j++) {
            int ii = i0 + ty * 4 + i, jj = j0 + tx * 4 + j;
            float v = acc[i][j];
            float dn = sqrtf(v + 1e-6f);
            float d2 = v * (1.f + 0.15f * cosf(dn));
            d2 = fmaxf(d2, 1e-6f);
            g_invd[(size_t)ii * S + jj] = 1.0f / d2;
        }
}

// ---------------------------------------------------------------------------
// Kernel 3: attention. Block = (b,h, 64-row tile). Loop 64-col tiles:
//   p = exp(min(|G_h| * m_i * m_j * invd, 50)), acc += p @ V, rowsum += sum(p)
//   out = acc / rowsum
// ---------------------------------------------------------------------------
__global__ void attn_kernel(const float* __restrict__ x,
                            const float* __restrict__ G, int S) {
    __shared__ float Vs[64][65];
    __shared__ float Ps[64][65];
    __shared__ float mi[64], mj[64], rowsum[64], rsp[64][4];

    int bh = blockIdx.y;
    int b = bh >> 4, h = bh & 15;
    int i0 = blockIdx.x * 64;
    int tid = threadIdx.x;
    int ty = tid >> 4, tx = tid & 15;
    float coef = fabsf(G[h]);
    const float* mrow = &g_masses[(b * NHEADS + h) * S];

    if (tid < 64) {
        mi[tid] = mrow[i0 + tid];
        rowsum[tid] = 0.f;
    }
    float acc[4][4] = {};

    for (int jt = 0; jt < S; jt += 64) {
        __syncthreads();                              // prev GEMM/rsp done
        if (tid < 64) mj[tid] = mrow[jt + tid];
#pragma unroll
        for (int v = 0; v < 16; v++) {                // load V tile [64][64]
            int e = v * 256 + tid;
            int r = e >> 6, c = e & 63;
            Vs[r][c] = x[((size_t)(b * S + jt + r)) * DM + h * HD + c];
        }
        __syncthreads();
#pragma unroll
        for (int v = 0; v < 16; v++) {                // P tile
            int e = v * 256 + tid;
            int r = e >> 6, c = e & 63;
            float f = coef * mi[r] * mj[c] * g_invd[(size_t)(i0 + r) * S + jt + c];
            Ps[r][c] = __expf(fminf(f, 50.f));
        }
        __syncthreads();
        {                                             // row-sum partials
            int r = tid >> 2, q = tid & 3;
            float s = 0.f;
#pragma unroll
            for (int c = 0; c < 16; c++) s += Ps[r][q * 16 + c];
            rsp[r][q] = s;
        }
#pragma unroll
        for (int kk = 0; kk < 64; kk++) {             // P @ V
            float a[4], bb[4];
#pragma unroll
            for (int i = 0; i < 4; i++) a[i] = Ps[ty * 4 + i][kk];
#pragma unroll
            for (int j = 0; j < 4; j++) bb[j] = Vs[kk][tx * 4 + j];
#pragma unroll
            for (int i = 0; i < 4; i++)
#pragma unroll
                for (int j = 0; j < 4; j++)
                    acc[i][j] = fmaf(a[i], bb[j], acc[i][j]);
        }
        __syncthreads();
        if (tid < 64)
            rowsum[tid] += rsp[tid][0] + rsp[tid][1] + rsp[tid][2] + rsp[tid][3];
    }
    __syncthreads();
    float rinv[4];
#pragma unroll
    for (int i = 0; i < 4; i++) rinv[i] = 1.0f / rowsum[ty * 4 + i];
#pragma unroll
    for (int i = 0; i < 4; i++)
#pragma unroll
        for (int j = 0; j < 4; j++)
            g_O[((size_t)(b * S + i0 + ty * 4 + i)) * DM + h * HD + tx * 4 + j] =
                acc[i][j] * rinv[i];
}

// ---------------------------------------------------------------------------
// Kernel 4: Y[n,j] = sum_k O[n,k] * Wout[j,k]   (Y = O @ Wout^T)
// 64x64 tile, K-chunk 16, 4x4 microtiles
// ---------------------------------------------------------------------------
__global__ void out_gemm(const float* __restrict__ W, float* __restrict__ Y) {
    __shared__ float As[16][65];   // [kk][row]
    __shared__ float Bs[16][65];   // [kk][col]
    int n0 = blockIdx.y * 64, j0 = blockIdx.x * 64;
    int tid = threadIdx.x;
    int ty = tid >> 4, tx = tid & 15;
    float acc[4][4] = {};

    for (int k0 = 0; k0 < DM; k0 += 16) {
        __syncthreads();
#pragma unroll
        for (int v = 0; v < 4; v++) {
            int e = v * 256 + tid;
            int r = e >> 4, kk = e & 15;
            As[kk][r] = g_O[(size_t)(n0 + r) * DM + k0 + kk];
            Bs[kk][r] = W[(size_t)(j0 + r) * DM + k0 + kk];
        }
        __syncthreads();
#pragma unroll
        for (int kk = 0; kk < 16; kk++) {
            float a[4], bb[4];
#pragma unroll
            for (int i = 0; i < 4; i++) a[i] = As[kk][ty * 4 + i];
#pragma unroll
            for (int j = 0; j < 4; j++) bb[j] = Bs[kk][tx * 4 + j];
#pragma unroll
            for (int i = 0; i < 4; i++)
#pragma unroll
                for (int j = 0; j < 4; j++)
                    acc[i][j] = fmaf(a[i], bb[j], acc[i][j]);
        }
    }
#pragma unroll
    for (int i = 0; i < 4; i++)
#pragma unroll
        for (int j = 0; j < 4; j++)
            Y[(size_t)(n0 + ty * 4 + i) * DM + j0 + tx * 4 + j] = acc[i][j];
}

// ---------------------------------------------------------------------------
extern "C" void kernel_launch(void* const* d_in, const int* in_sizes, int n_in,
                              void* d_out, int out_size) {
    const float* x   = (const float*)d_in[0];   // [B,S,1024]
    const float* pos = (const float*)d_in[1];   // [S,64]
    const float* Wm  = (const float*)d_in[2];   // [16,64]
    const float* G   = (const float*)d_in[3];   // [16]
    const float* Wo  = (const float*)d_in[4];   // [1024,1024]
    float* out = (float*)d_out;                 // [B,S,1024]

    int S = in_sizes[1] / PDIM;
    int B = in_sizes[0] / (S * DM);

    // 1) masses: one warp per (b,h,s)
    int nwarps = B * NHEADS * S;
    mass_kernel<<<nwarps / 8, 256>>>(x, Wm, S);

    // 2) modified inverse squared distances (S x S)
    dim3 gd(S / 64, S / 64);
    dist_kernel<<<gd, 256>>>(pos, S);

    // 3) gravitational attention per (b,h), 64-row tiles
    dim3 ga(S / 64, B * NHEADS);
    attn_kernel<<<ga, 256>>>(x, G, S);

    // 4) output projection
    dim3 gg(DM / 64, (B * S) / 64);
    out_gemm<<<gg, 256>>>(Wo, out);
}

// round 2
// speedup vs baseline: 1.8758x; 1.8758x over previous
#include <cuda_runtime.h>
#include <math.h>
#include <stdint.h>

#define NHEADS 16
#define HD 64
#define DM 1024
#define PDIM 64
#define MAXS 2048
#define MAXB 2

// scratch (device globals — no runtime allocation)
__device__ float g_masses[MAXB * NHEADS * MAXS];              // [B,H,S]
__device__ float g_invd[(size_t)MAXS * MAXS];                 // 1 / dist_sq_mod
__device__ float g_O[(size_t)MAXB * MAXS * DM];               // attention output

// tf32 convert (round-to-nearest). Result bits are valid fp32 (low 13 bits 0).
__device__ __forceinline__ uint32_t f2tf32(float f) {
    uint32_t u;
    asm("cvt.rna.tf32.f32 %0, %1;" : "=r"(u) : "f"(f));
    return u;
}

// D += A(16x8 tf32, row) * B(8x8 tf32, col), fp32 accum
__device__ __forceinline__ void mma_tf32(float* d, const uint32_t* a, const uint32_t* b) {
    asm volatile(
        "mma.sync.aligned.m16n8k8.row.col.f32.tf32.tf32.f32 "
        "{%0,%1,%2,%3}, {%4,%5,%6,%7}, {%8,%9}, {%0,%1,%2,%3};"
        : "+f"(d[0]), "+f"(d[1]), "+f"(d[2]), "+f"(d[3])
        : "r"(a[0]), "r"(a[1]), "r"(a[2]), "r"(a[3]), "r"(b[0]), "r"(b[1]));
}

// ---------------------------------------------------------------------------
// Kernel 1: masses[b,h,s] = softplus( dot(xh[b,s,h,:], W_mass[h,:]) )
// ---------------------------------------------------------------------------
__global__ void mass_kernel(const float* __restrict__ x,
                            const float* __restrict__ Wm, int S) {
    int gw   = (blockIdx.x * 256 + threadIdx.x) >> 5;
    int lane = threadIdx.x & 31;
    int s = gw % S;
    int h = (gw / S) & (NHEADS - 1);
    int b = gw / (S * NHEADS);
    const float* xr = x + ((size_t)(b * S + s)) * DM + h * HD;
    float t = xr[lane] * Wm[h * HD + lane] + xr[lane + 32] * Wm[h * HD + lane + 32];
#pragma unroll
    for (int o = 16; o; o >>= 1) t += __shfl_xor_sync(0xffffffffu, t, o);
    if (lane == 0) {
        float m = (t > 20.f) ? t : log1pf(expf(t));
        g_masses[(b * NHEADS + h) * S + s] = m;
    }
}

// ---------------------------------------------------------------------------
// Kernel 2: g_invd[i,j] = 1 / max( d2*(1+0.15*cos(sqrt(d2+1e-6))), 1e-6 )
// ---------------------------------------------------------------------------
__global__ void dist_kernel(const float* __restrict__ pos, int S) {
    __shared__ float Pi[PDIM][65];
    __shared__ float Pj[PDIM][65];
    int i0 = blockIdx.x * 64, j0 = blockIdx.y * 64;
    int tid = threadIdx.x;
#pragma unroll
    for (int v = 0; v < 16; v++) {
        int e = v * 256 + tid;
        int r = e >> 6, p = e & 63;
        Pi[p][r] = pos[(size_t)(i0 + r) * PDIM + p];
        Pj[p][r] = pos[(size_t)(j0 + r) * PDIM + p];
    }
    __syncthreads();
    int ty = tid >> 4, tx = tid & 15;
    float acc[4][4] = {};
#pragma unroll
    for (int p = 0; p < PDIM; p++) {
        float a[4], bb[4];
#pragma unroll
        for (int i = 0; i < 4; i++) a[i] = Pi[p][ty * 4 + i];
#pragma unroll
        for (int j = 0; j < 4; j++) bb[j] = Pj[p][tx * 4 + j];
#pragma unroll
        for (int i = 0; i < 4; i++)
#pragma unroll
            for (int j = 0; j < 4; j++) {
                float d = a[i] - bb[j];
                acc[i][j] = fmaf(d, d, acc[i][j]);
            }
    }
#pragma unroll
    for (int i = 0; i < 4; i++)
#pragma unroll
        for (int j = 0; j < 4; j++) {
            int ii = i0 + ty * 4 + i, jj = j0 + tx * 4 + j;
            float v = acc[i][j];
            float dn = sqrtf(v + 1e-6f);
            float d2 = v * (1.f + 0.15f * cosf(dn));
            d2 = fmaxf(d2, 1e-6f);
            g_invd[(size_t)ii * S + jj] = 1.0f / d2;
        }
}

// ---------------------------------------------------------------------------
// Kernel 3: attention with tf32 tensor-core P@V.
// Block = (64-row i-tile, b*h). 256 threads / 8 warps.
// Warp tile: 16 rows x 32 cols of the 64x64 output.
// ---------------------------------------------------------------------------
__global__ void attn_kernel(const float* __restrict__ x,
                            const float* __restrict__ G, int S) {
    __shared__ uint32_t Ps[64][68];      // P tile (tf32 bits), conflict-free frags
    __shared__ uint32_t Vs[64][72];      // V tile [k][n] (tf32 bits)
    __shared__ float mi[64], mj[64], rowsum[64], rsp[64][4];

    int bh = blockIdx.y;
    int b = bh >> 4, h = bh & 15;
    int i0 = blockIdx.x * 64;
    int tid = threadIdx.x;
    int w = tid >> 5, lane = tid & 31;
    int g = lane >> 2, t = lane & 3;
    int wm = (w >> 1) * 16;              // row offset of warp tile
    int wn = (w & 1) * 32;               // col offset of warp tile
    float coef = fabsf(G[h]);
    const float* mrow = &g_masses[(b * NHEADS + h) * S];

    if (tid < 64) { mi[tid] = mrow[i0 + tid]; rowsum[tid] = 0.f; }
    float acc[4][4] = {};                // [ntile][4]

    for (int jt = 0; jt < S; jt += 64) {
        __syncthreads();                                // all prev-iter reads done
        if (tid < 64) mj[tid] = mrow[jt + tid];
#pragma unroll
        for (int v = 0; v < 16; v++) {                  // V tile [64 k][64 n]
            int e = v * 256 + tid;
            int r = e >> 6, c = e & 63;
            Vs[r][c] = f2tf32(x[((size_t)(b * S + jt + r)) * DM + h * HD + c]);
        }
        __syncthreads();                                // mj ready
#pragma unroll
        for (int v = 0; v < 16; v++) {                  // P tile
            int e = v * 256 + tid;
            int r = e >> 6, c = e & 63;
            float f = coef * mi[r] * mj[c] * g_invd[(size_t)(i0 + r) * S + jt + c];
            Ps[r][c] = f2tf32(__expf(fminf(f, 50.f)));
        }
        __syncthreads();                                // Ps/Vs ready
        {                                               // row-sum partials
            int r = tid >> 2, q = tid & 3;
            float s = 0.f;
#pragma unroll
            for (int c = 0; c < 16; c++) s += __uint_as_float(Ps[r][q * 16 + c]);
            rsp[r][q] = s;
        }
#pragma unroll
        for (int ks = 0; ks < 8; ks++) {                // P @ V on tensor pipe
            int k = ks * 8;
            uint32_t a[4];
            a[0] = Ps[wm + g][k + t];
            a[1] = Ps[wm + g + 8][k + t];
            a[2] = Ps[wm + g][k + t + 4];
            a[3] = Ps[wm + g + 8][k + t + 4];
#pragma unroll
            for (int nt = 0; nt < 4; nt++) {
                uint32_t bf[2];
                bf[0] = Vs[k + t][wn + nt * 8 + g];
                bf[1] = Vs[k + t + 4][wn + nt * 8 + g];
                mma_tf32(acc[nt], a, bf);
            }
        }
        __syncthreads();                                // rsp written
        if (tid < 64)
            rowsum[tid] += rsp[tid][0] + rsp[tid][1] + rsp[tid][2] + rsp[tid][3];
    }
    __syncthreads();
    float r0 = 1.0f / rowsum[wm + g];
    float r1 = 1.0f / rowsum[wm + g + 8];
    size_t base0 = ((size_t)(b * S + i0 + wm + g)) * DM + h * HD;
    size_t base1 = ((size_t)(b * S + i0 + wm + g + 8)) * DM + h * HD;
#pragma unroll
    for (int nt = 0; nt < 4; nt++) {
        int c = wn + nt * 8 + 2 * t;
        g_O[base0 + c]     = acc[nt][0] * r0;
        g_O[base0 + c + 1] = acc[nt][1] * r0;
        g_O[base1 + c]     = acc[nt][2] * r1;
        g_O[base1 + c + 1] = acc[nt][3] * r1;
    }
}

// ---------------------------------------------------------------------------
// Kernel 4: Y = O @ Wout^T on tf32 tensor cores.
// 128x128 block tile, 256 threads / 8 warps, warp tile 64x32, kchunk 32.
// XOR-swizzled smem (conflict-free stores AND fragment loads).
// ---------------------------------------------------------------------------
#define SW(r, c) ((c) ^ (((r) & 7) << 2))

__global__ void out_gemm(const float* __restrict__ W, float* __restrict__ Y) {
    __shared__ uint32_t As[128][32];     // O tile  [m][k], swizzled
    __shared__ uint32_t Bs[128][32];     // W tile  [j][k], swizzled
    int n0 = blockIdx.y * 128, j0 = blockIdx.x * 128;
    int tid = threadIdx.x;
    int w = tid >> 5, lane = tid & 31;
    int g = lane >> 2, t = lane & 3;
    int wm = (w >> 2) * 64, wn = (w & 3) * 32;

    float acc[4][4][4] = {};             // [mtile][ntile][4]

    for (int k0 = 0; k0 < DM; k0 += 32) {
        __syncthreads();
#pragma unroll
        for (int v = 0; v < 16; v++) {
            int e = v * 256 + tid;
            int r = e >> 5, c = e & 31;
            As[r][SW(r, c)] = f2tf32(g_O[(size_t)(n0 + r) * DM + k0 + c]);
            Bs[r][SW(r, c)] = f2tf32(W[(size_t)(j0 + r) * DM + k0 + c]);
        }
        __syncthreads();
#pragma unroll
        for (int ks = 0; ks < 4; ks++) {
            int k = ks * 8;
            uint32_t a[4][4], bf[4][2];
#pragma unroll
            for (int mt = 0; mt < 4; mt++) {
                int r = wm + mt * 16 + g;
                a[mt][0] = As[r][SW(r, k + t)];
                a[mt][1] = As[r + 8][SW(r + 8, k + t)];
                a[mt][2] = As[r][SW(r, k + t + 4)];
                a[mt][3] = As[r + 8][SW(r + 8, k + t + 4)];
            }
#pragma unroll
            for (int nt = 0; nt < 4; nt++) {
                int r = wn + nt * 8 + g;
                bf[nt][0] = Bs[r][SW(r, k + t)];
                bf[nt][1] = Bs[r][SW(r, k + t + 4)];
            }
#pragma unroll
            for (int mt = 0; mt < 4; mt++)
#pragma unroll
                for (int nt = 0; nt < 4; nt++)
                    mma_tf32(acc[mt][nt], a[mt], bf[nt]);
        }
    }
#pragma unroll
    for (int mt = 0; mt < 4; mt++) {
        int m = n0 + wm + mt * 16 + g;
#pragma unroll
        for (int nt = 0; nt < 4; nt++) {
            int j = j0 + wn + nt * 8 + 2 * t;
            Y[(size_t)m * DM + j]           = acc[mt][nt][0];
            Y[(size_t)m * DM + j + 1]       = acc[mt][nt][1];
            Y[(size_t)(m + 8) * DM + j]     = acc[mt][nt][2];
            Y[(size_t)(m + 8) * DM + j + 1] = acc[mt][nt][3];
        }
    }
}

// ---------------------------------------------------------------------------
extern "C" void kernel_launch(void* const* d_in, const int* in_sizes, int n_in,
                              void* d_out, int out_size) {
    const float* x   = (const float*)d_in[0];   // [B,S,1024]
    const float* pos = (const float*)d_in[1];   // [S,64]
    const float* Wm  = (const float*)d_in[2];   // [16,64]
    const float* G   = (const float*)d_in[3];   // [16]
    const float* Wo  = (const float*)d_in[4];   // [1024,1024]
    float* out = (float*)d_out;                 // [B,S,1024]

    int S = in_sizes[1] / PDIM;
    int B = in_sizes[0] / (S * DM);

    int nwarps = B * NHEADS * S;
    mass_kernel<<<nwarps / 8, 256>>>(x, Wm, S);

    dim3 gd(S / 64, S / 64);
    dist_kernel<<<gd, 256>>>(pos, S);

    dim3 ga(S / 64, B * NHEADS);
    attn_kernel<<<ga, 256>>>(x, G, S);

    dim3 gg(DM / 128, (B * S) / 128);
    out_gemm<<<gg, 256>>>(Wo, out);
}

// round 3
// speedup vs baseline: 4.3182x; 2.3020x over previous
#include <cuda_runtime.h>
#include <math.h>
#include <stdint.h>

#define NHEADS 16
#define HD 64
#define DM 1024
#define PDIM 64
#define MAXS 2048
#define MAXB 2

// scratch (device globals — no runtime allocation)
__device__ float g_masses[MAXB * NHEADS * MAXS];              // [B,H,S] (pre-scaled by |G_h|)
__device__ float g_invd[(size_t)MAXS * MAXS];                 // 1 / dist_sq_mod
__device__ float g_O[(size_t)MAXB * MAXS * DM];               // attention output (tf32-rounded bits)
__device__ float g_Wc[(size_t)DM * DM];                       // W_out, tf32-rounded bits

// tf32 convert (round-to-nearest). Result bits are valid fp32 (low 13 bits 0).
__device__ __forceinline__ uint32_t f2tf32(float f) {
    uint32_t u;
    asm("cvt.rna.tf32.f32 %0, %1;" : "=r"(u) : "f"(f));
    return u;
}

// D += A(16x8 tf32, row) * B(8x8 tf32, col), fp32 accum
__device__ __forceinline__ void mma_tf32(float* d, const uint32_t* a, const uint32_t* b) {
    asm volatile(
        "mma.sync.aligned.m16n8k8.row.col.f32.tf32.tf32.f32 "
        "{%0,%1,%2,%3}, {%4,%5,%6,%7}, {%8,%9}, {%0,%1,%2,%3};"
        : "+f"(d[0]), "+f"(d[1]), "+f"(d[2]), "+f"(d[3])
        : "r"(a[0]), "r"(a[1]), "r"(a[2]), "r"(a[3]), "r"(b[0]), "r"(b[1]));
}

// ---------------------------------------------------------------------------
// Kernel 1: masses[b,h,s] = |G_h| * softplus( dot(xh[b,s,h,:], W_mass[h,:]) )
// ---------------------------------------------------------------------------
__global__ void mass_kernel(const float* __restrict__ x,
                            const float* __restrict__ Wm,
                            const float* __restrict__ G, int S) {
    int gw   = (blockIdx.x * 256 + threadIdx.x) >> 5;
    int lane = threadIdx.x & 31;
    int s = gw % S;
    int h = (gw / S) & (NHEADS - 1);
    int b = gw / (S * NHEADS);
    const float* xr = x + ((size_t)(b * S + s)) * DM + h * HD;
    float t = xr[lane] * Wm[h * HD + lane] + xr[lane + 32] * Wm[h * HD + lane + 32];
#pragma unroll
    for (int o = 16; o; o >>= 1) t += __shfl_xor_sync(0xffffffffu, t, o);
    if (lane == 0) {
        float m = (t > 20.f) ? t : log1pf(expf(t));
        g_masses[(b * NHEADS + h) * S + s] = m;
    }
}

// ---------------------------------------------------------------------------
// Kernel 1b: pre-round W_out to tf32 bits
// ---------------------------------------------------------------------------
__global__ void wcvt_kernel(const float* __restrict__ W) {
    int i = blockIdx.x * 256 + threadIdx.x;
    float4 v = *(const float4*)&W[(size_t)i * 4];
    uint4 o;
    o.x = f2tf32(v.x); o.y = f2tf32(v.y); o.z = f2tf32(v.z); o.w = f2tf32(v.w);
    *(uint4*)&g_Wc[(size_t)i * 4] = o;
}

// ---------------------------------------------------------------------------
// Kernel 2: g_invd[i,j] = 1 / max( d2*(1+0.15*cos(sqrt(d2+1e-6))), 1e-6 )
// direct (a-b)^2 accumulation: diagonal exactly 0
// ---------------------------------------------------------------------------
__global__ void dist_kernel(const float* __restrict__ pos, int S) {
    __shared__ float Pi[PDIM][65];
    __shared__ float Pj[PDIM][65];
    int i0 = blockIdx.x * 64, j0 = blockIdx.y * 64;
    int tid = threadIdx.x;
#pragma unroll
    for (int v = 0; v < 16; v++) {
        int e = v * 256 + tid;
        int r = e >> 6, p = e & 63;
        Pi[p][r] = pos[(size_t)(i0 + r) * PDIM + p];
        Pj[p][r] = pos[(size_t)(j0 + r) * PDIM + p];
    }
    __syncthreads();
    int ty = tid >> 4, tx = tid & 15;
    float acc[4][4] = {};
#pragma unroll
    for (int p = 0; p < PDIM; p++) {
        float a[4], bb[4];
#pragma unroll
        for (int i = 0; i < 4; i++) a[i] = Pi[p][ty * 4 + i];
#pragma unroll
        for (int j = 0; j < 4; j++) bb[j] = Pj[p][tx * 4 + j];
#pragma unroll
        for (int i = 0; i < 4; i++)
#pragma unroll
            for (int j = 0; j < 4; j++) {
                float d = a[i] - bb[j];
                acc[i][j] = fmaf(d, d, acc[i][j]);
            }
    }
#pragma unroll
    for (int i = 0; i < 4; i++)
#pragma unroll
        for (int j = 0; j < 4; j++) {
            int ii = i0 + ty * 4 + i, jj = j0 + tx * 4 + j;
            float v = acc[i][j];
            float dn = sqrtf(v + 1e-6f);
            float d2 = v * (1.f + 0.15f * cosf(dn));
            d2 = fmaxf(d2, 1e-6f);
            g_invd[(size_t)ii * S + jj] = 1.0f / d2;
        }
}

// ---------------------------------------------------------------------------
// Kernel 3: attention, tf32 tensor cores, 128x128 P tiles.
// Block = (128-row i-tile, b*h), 256 threads / 8 warps.
// Warp w owns 16 full output rows (all 64 cols) -> rowsum computed in-MMA
// via a ones-column B fragment. Output written tf32-rounded.
// ---------------------------------------------------------------------------
__global__ __launch_bounds__(256, 2)
void attn_kernel(const float* __restrict__ x,
                 const float* __restrict__ G, int S) {
    extern __shared__ uint32_t sm_a[];
    uint32_t* Ps = sm_a;                         // [128][128] swizzled
    uint32_t* Vs = sm_a + 128 * 128;             // [128][72]
    float* mi = (float*)(sm_a + 128 * 128 + 128 * 72);  // [128]
    float* mj = mi + 128;                        // [128]

    int bh = blockIdx.y;
    int b = bh >> 4, h = bh & 15;
    int i0 = blockIdx.x * 128;
    int tid = threadIdx.x;
    int w = tid >> 5, lane = tid & 31;
    int g = lane >> 2, t = lane & 3;
    int wm = w * 16;
    int swz = g << 2;
    const float* mrow = &g_masses[(b * NHEADS + h) * S];
    float coef = fabsf(G[h]);

    if (tid < 128) mi[tid] = coef * mrow[i0 + tid];

    float acc[8][4] = {};
    float sacc[4] = {};
    const uint32_t ONE = 0x3f800000u;

    for (int jt = 0; jt < S; jt += 128) {
        __syncthreads();                             // prev-iter mma reads done
        if (tid < 128) mj[tid] = mrow[jt + tid];
        __syncthreads();                             // mj visible

        // V tile [128 k][64 n] -> tf32
#pragma unroll
        for (int v = 0; v < 8; v++) {
            int idx4 = v * 256 + tid;
            int r = idx4 >> 4, c4 = idx4 & 15;
            float4 xv = *(const float4*)&x[((size_t)(b * S + jt + r)) * DM + h * HD + c4 * 4];
            uint4 o;
            o.x = f2tf32(xv.x); o.y = f2tf32(xv.y); o.z = f2tf32(xv.z); o.w = f2tf32(xv.w);
            *(uint4*)&Vs[r * 72 + c4 * 4] = o;
        }
        // P tile [128 i][128 j]: whole warp works one row at a time
#pragma unroll
        for (int v = 0; v < 16; v++) {
            int r = v * 8 + (tid >> 5);
            float cm = mi[r];
            float4 dv = *(const float4*)&g_invd[(size_t)(i0 + r) * S + jt + 4 * lane];
            float4 mv = *(const float4*)&mj[4 * lane];
            uint4 o;
            o.x = f2tf32(__expf(fminf(cm * mv.x * dv.x, 50.f)));
            o.y = f2tf32(__expf(fminf(cm * mv.y * dv.y, 50.f)));
            o.z = f2tf32(__expf(fminf(cm * mv.z * dv.z, 50.f)));
            o.w = f2tf32(__expf(fminf(cm * mv.w * dv.w, 50.f)));
            *(uint4*)&Ps[r * 128 + ((4 * lane) ^ ((r & 7) << 2))] = o;
        }
        __syncthreads();                             // tiles ready

#pragma unroll
        for (int ks = 0; ks < 16; ks++) {
            int k = ks * 8;
            uint32_t a[4];
            a[0] = Ps[(wm + g) * 128 + ((k + t) ^ swz)];
            a[1] = Ps[(wm + g + 8) * 128 + ((k + t) ^ swz)];
            a[2] = Ps[(wm + g) * 128 + ((k + t + 4) ^ swz)];
            a[3] = Ps[(wm + g + 8) * 128 + ((k + t + 4) ^ swz)];
#pragma unroll
            for (int nt = 0; nt < 8; nt++) {
                uint32_t bf[2];
                bf[0] = Vs[(k + t) * 72 + nt * 8 + g];
                bf[1] = Vs[(k + t + 4) * 72 + nt * 8 + g];
                mma_tf32(acc[nt], a, bf);
            }
            uint32_t ones[2] = {ONE, ONE};
            mma_tf32(sacc, a, ones);                 // rowsum accumulator
        }
    }

    float r0 = 1.0f / sacc[0];
    float r1 = 1.0f / sacc[2];
    size_t base0 = ((size_t)(b * S + i0 + wm + g)) * DM + h * HD;
    size_t base1 = base0 + (size_t)8 * DM;
#pragma unroll
    for (int nt = 0; nt < 8; nt++) {
        int c = nt * 8 + 2 * t;
        float2 v0, v1;
        v0.x = __uint_as_float(f2tf32(acc[nt][0] * r0));
        v0.y = __uint_as_float(f2tf32(acc[nt][1] * r0));
        v1.x = __uint_as_float(f2tf32(acc[nt][2] * r1));
        v1.y = __uint_as_float(f2tf32(acc[nt][3] * r1));
        *(float2*)&g_O[base0 + c] = v0;
        *(float2*)&g_O[base1 + c] = v1;
    }
}

// ---------------------------------------------------------------------------
// Kernel 4: Y = O @ Wc^T, tf32 tensor cores, cp.async double-buffered.
// 128x128 block tile, 8 warps, warp tile 64x32, K-chunk 32.
// Inputs already tf32-rounded (g_O by attn, g_Wc by wcvt).
// ---------------------------------------------------------------------------
__global__ __launch_bounds__(256, 2)
void out_gemm(float* __restrict__ Y) {
    extern __shared__ uint32_t sm_g[];
    uint32_t* As = sm_g;                 // [2][128][32] swizzled
    uint32_t* Bs = sm_g + 2 * 128 * 32;  // [2][128][32] swizzled

    int n0 = blockIdx.y * 128, j0 = blockIdx.x * 128;
    int tid = threadIdx.x;
    int w = tid >> 5, lane = tid & 31;
    int g = lane >> 2, t = lane & 3;
    int wm = (w >> 2) * 64, wn = (w & 3) * 32;
    int swz = g << 2;

    float acc[4][4][4] = {};

    // per-thread copy coordinates (4 float4 per array per chunk)
    int cr[4], cc[4];
#pragma unroll
    for (int v = 0; v < 4; v++) {
        int idx4 = v * 256 + tid;
        cr[v] = idx4 >> 3;
        cc[v] = (idx4 & 7) * 4;
    }

#define OG_ISSUE(buf, k0)                                                        \
    do {                                                                         \
        _Pragma("unroll")                                                        \
        for (int v = 0; v < 4; v++) {                                            \
            int r = cr[v], c = cc[v];                                            \
            int so = r * 32 + (c ^ ((r & 7) << 2));                              \
            uint32_t dA = (uint32_t)__cvta_generic_to_shared(&As[(buf)*4096 + so]); \
            const float* sA = &g_O[(size_t)(n0 + r) * DM + (k0) + c];            \
            asm volatile("cp.async.cg.shared.global [%0], [%1], 16;" ::"r"(dA), "l"(sA)); \
            uint32_t dB = (uint32_t)__cvta_generic_to_shared(&Bs[(buf)*4096 + so]); \
            const float* sB = &g_Wc[(size_t)(j0 + r) * DM + (k0) + c];           \
            asm volatile("cp.async.cg.shared.global [%0], [%1], 16;" ::"r"(dB), "l"(sB)); \
        }                                                                        \
        asm volatile("cp.async.commit_group;");                                  \
    } while (0)

    OG_ISSUE(0, 0);

    for (int ki = 0; ki < DM / 32; ki++) {
        asm volatile("cp.async.wait_group 0;");
        __syncthreads();
        if (ki + 1 < DM / 32) OG_ISSUE((ki + 1) & 1, (ki + 1) * 32);

        const uint32_t* Ab = &As[(ki & 1) * 4096];
        const uint32_t* Bb = &Bs[(ki & 1) * 4096];
#pragma unroll
        for (int ks = 0; ks < 4; ks++) {
            int k = ks * 8;
            uint32_t a[4][4], bf[4][2];
#pragma unroll
            for (int mt = 0; mt < 4; mt++) {
                int r = wm + mt * 16 + g;
                a[mt][0] = Ab[r * 32 + ((k + t) ^ swz)];
                a[mt][1] = Ab[(r + 8) * 32 + ((k + t) ^ swz)];
                a[mt][2] = Ab[r * 32 + ((k + t + 4) ^ swz)];
                a[mt][3] = Ab[(r + 8) * 32 + ((k + t + 4) ^ swz)];
            }
#pragma unroll
            for (int nt = 0; nt < 4; nt++) {
                int r = wn + nt * 8 + g;
                bf[nt][0] = Bb[r * 32 + ((k + t) ^ swz)];
                bf[nt][1] = Bb[r * 32 + ((k + t + 4) ^ swz)];
            }
#pragma unroll
            for (int mt = 0; mt < 4; mt++)
#pragma unroll
                for (int nt = 0; nt < 4; nt++)
                    mma_tf32(acc[mt][nt], a[mt], bf[nt]);
        }
    }
#pragma unroll
    for (int mt = 0; mt < 4; mt++) {
        int m = n0 + wm + mt * 16 + g;
#pragma unroll
        for (int nt = 0; nt < 4; nt++) {
            int j = j0 + wn + nt * 8 + 2 * t;
            float2 v0, v1;
            v0.x = acc[mt][nt][0]; v0.y = acc[mt][nt][1];
            v1.x = acc[mt][nt][2]; v1.y = acc[mt][nt][3];
            *(float2*)&Y[(size_t)m * DM + j] = v0;
            *(float2*)&Y[(size_t)(m + 8) * DM + j] = v1;
        }
    }
}

// ---------------------------------------------------------------------------
extern "C" void kernel_launch(void* const* d_in, const int* in_sizes, int n_in,
                              void* d_out, int out_size) {
    const float* x   = (const float*)d_in[0];   // [B,S,1024]
    const float* pos = (const float*)d_in[1];   // [S,64]
    const float* Wm  = (const float*)d_in[2];   // [16,64]
    const float* G   = (const float*)d_in[3];   // [16]
    const float* Wo  = (const float*)d_in[4];   // [1024,1024]
    float* out = (float*)d_out;                 // [B,S,1024]

    int S = in_sizes[1] / PDIM;
    int B = in_sizes[0] / (S * DM);

    static const int ATTN_SMEM = (128 * 128 + 128 * 72 + 256) * 4;
    static const int GEMM_SMEM = 4 * 128 * 32 * 4;
    cudaFuncSetAttribute(attn_kernel, cudaFuncAttributeMaxDynamicSharedMemorySize, ATTN_SMEM);
    cudaFuncSetAttribute(out_gemm, cudaFuncAttributeMaxDynamicSharedMemorySize, GEMM_SMEM);

    int nwarps = B * NHEADS * S;
    mass_kernel<<<nwarps / 8, 256>>>(x, Wm, G, S);

    wcvt_kernel<<<DM * DM / 1024, 256>>>(Wo);

    dim3 gd(S / 64, S / 64);
    dist_kernel<<<gd, 256>>>(pos, S);

    dim3 ga(S / 128, B * NHEADS);
    attn_kernel<<<ga, 256, ATTN_SMEM>>>(x, G, S);

    dim3 gg(DM / 128, (B * S) / 128);
    out_gemm<<<gg, 256, GEMM_SMEM>>>(out);
}

// round 4
// speedup vs baseline: 4.3201x; 1.0004x over previous
#include <cuda_runtime.h>
#include <math.h>
#include <stdint.h>

#define NHEADS 16
#define HD 64
#define DM 1024
#define PDIM 64
#define MAXS 2048
#define MAXB 2

// scratch (device globals — no runtime allocation)
__device__ float g_masses[MAXB * NHEADS * MAXS];              // [B,H,S] (pre-scaled by |G_h|)
__device__ float g_invd[(size_t)MAXS * MAXS];                 // 1 / dist_sq_mod
__device__ float g_O[(size_t)MAXB * MAXS * DM];               // attention output (tf32-rounded bits)
__device__ float g_Wc[(size_t)DM * DM];                       // W_out, tf32-rounded bits

// tf32 convert (round-to-nearest). Result bits are valid fp32 (low 13 bits 0).
__device__ __forceinline__ uint32_t f2tf32(float f) {
    uint32_t u;
    asm("cvt.rna.tf32.f32 %0, %1;" : "=r"(u) : "f"(f));
    return u;
}

// D += A(16x8 tf32, row) * B(8x8 tf32, col), fp32 accum
__device__ __forceinline__ void mma_tf32(float* d, const uint32_t* a, const uint32_t* b) {
    asm volatile(
        "mma.sync.aligned.m16n8k8.row.col.f32.tf32.tf32.f32 "
        "{%0,%1,%2,%3}, {%4,%5,%6,%7}, {%8,%9}, {%0,%1,%2,%3};"
        : "+f"(d[0]), "+f"(d[1]), "+f"(d[2]), "+f"(d[3])
        : "r"(a[0]), "r"(a[1]), "r"(a[2]), "r"(a[3]), "r"(b[0]), "r"(b[1]));
}

// ---------------------------------------------------------------------------
// Kernel 1: masses[b,h,s] = |G_h| * softplus( dot(xh[b,s,h,:], W_mass[h,:]) )
// ---------------------------------------------------------------------------
__global__ void mass_kernel(const float* __restrict__ x,
                            const float* __restrict__ Wm,
                            const float* __restrict__ G, int S) {
    int gw   = (blockIdx.x * 256 + threadIdx.x) >> 5;
    int lane = threadIdx.x & 31;
    int s = gw % S;
    int h = (gw / S) & (NHEADS - 1);
    int b = gw / (S * NHEADS);
    const float* xr = x + ((size_t)(b * S + s)) * DM + h * HD;
    float t = xr[lane] * Wm[h * HD + lane] + xr[lane + 32] * Wm[h * HD + lane + 32];
#pragma unroll
    for (int o = 16; o; o >>= 1) t += __shfl_xor_sync(0xffffffffu, t, o);
    if (lane == 0) {
        float m = (t > 20.f) ? t : log1pf(expf(t));
        g_masses[(b * NHEADS + h) * S + s] = m;
    }
}

// ---------------------------------------------------------------------------
// Kernel 1b: pre-round W_out to tf32 bits
// ---------------------------------------------------------------------------
__global__ void wcvt_kernel(const float* __restrict__ W) {
    int i = blockIdx.x * 256 + threadIdx.x;
    float4 v = *(const float4*)&W[(size_t)i * 4];
    uint4 o;
    o.x = f2tf32(v.x); o.y = f2tf32(v.y); o.z = f2tf32(v.z); o.w = f2tf32(v.w);
    *(uint4*)&g_Wc[(size_t)i * 4] = o;
}

// ---------------------------------------------------------------------------
// Kernel 2: g_invd[i,j] = 1 / max( d2*(1+0.15*cos(sqrt(d2+1e-6))), 1e-6 )
// direct (a-b)^2 accumulation: diagonal exactly 0
// ---------------------------------------------------------------------------
__global__ void dist_kernel(const float* __restrict__ pos, int S) {
    __shared__ float Pi[PDIM][65];
    __shared__ float Pj[PDIM][65];
    int i0 = blockIdx.x * 64, j0 = blockIdx.y * 64;
    int tid = threadIdx.x;
#pragma unroll
    for (int v = 0; v < 16; v++) {
        int e = v * 256 + tid;
        int r = e >> 6, p = e & 63;
        Pi[p][r] = pos[(size_t)(i0 + r) * PDIM + p];
        Pj[p][r] = pos[(size_t)(j0 + r) * PDIM + p];
    }
    __syncthreads();
    int ty = tid >> 4, tx = tid & 15;
    float acc[4][4] = {};
#pragma unroll
    for (int p = 0; p < PDIM; p++) {
        float a[4], bb[4];
#pragma unroll
        for (int i = 0; i < 4; i++) a[i] = Pi[p][ty * 4 + i];
#pragma unroll
        for (int j = 0; j < 4; j++) bb[j] = Pj[p][tx * 4 + j];
#pragma unroll
        for (int i = 0; i < 4; i++)
#pragma unroll
            for (int j = 0; j < 4; j++) {
                float d = a[i] - bb[j];
                acc[i][j] = fmaf(d, d, acc[i][j]);
            }
    }
#pragma unroll
    for (int i = 0; i < 4; i++)
#pragma unroll
        for (int j = 0; j < 4; j++) {
            int ii = i0 + ty * 4 + i, jj = j0 + tx * 4 + j;
            float v = acc[i][j];
            float dn = sqrtf(v + 1e-6f);
            float d2 = v * (1.f + 0.15f * cosf(dn));
            d2 = fmaxf(d2, 1e-6f);
            g_invd[(size_t)ii * S + jj] = 1.0f / d2;
        }
}

// ---------------------------------------------------------------------------
// Kernel 3: attention, tf32 tensor cores, 128x128 P tiles.
// Block = (128-row i-tile, b*h), 256 threads / 8 warps.
// Warp w owns 16 full output rows (all 64 cols) -> rowsum computed in-MMA
// via a ones-column B fragment. Output written tf32-rounded.
// ---------------------------------------------------------------------------
__global__ __launch_bounds__(256, 2)
void attn_kernel(const float* __restrict__ x,
                 const float* __restrict__ G, int S) {
    extern __shared__ uint32_t sm_a[];
    uint32_t* Ps = sm_a;                         // [128][128] swizzled
    uint32_t* Vs = sm_a + 128 * 128;             // [128][72]
    float* mi = (float*)(sm_a + 128 * 128 + 128 * 72);  // [128]
    float* mj = mi + 128;                        // [128]

    int bh = blockIdx.y;
    int b = bh >> 4, h = bh & 15;
    int i0 = blockIdx.x * 128;
    int tid = threadIdx.x;
    int w = tid >> 5, lane = tid & 31;
    int g = lane >> 2, t = lane & 3;
    int wm = w * 16;
    int swz = g << 2;
    const float* mrow = &g_masses[(b * NHEADS + h) * S];
    float coef = fabsf(G[h]);

    if (tid < 128) mi[tid] = coef * mrow[i0 + tid];

    float acc[8][4] = {};
    float sacc[4] = {};
    const uint32_t ONE = 0x3f800000u;

    for (int jt = 0; jt < S; jt += 128) {
        __syncthreads();                             // prev-iter mma reads done
        if (tid < 128) mj[tid] = mrow[jt + tid];
        __syncthreads();                             // mj visible

        // V tile [128 k][64 n] -> tf32
#pragma unroll
        for (int v = 0; v < 8; v++) {
            int idx4 = v * 256 + tid;
            int r = idx4 >> 4, c4 = idx4 & 15;
            float4 xv = *(const float4*)&x[((size_t)(b * S + jt + r)) * DM + h * HD + c4 * 4];
            uint4 o;
            o.x = f2tf32(xv.x); o.y = f2tf32(xv.y); o.z = f2tf32(xv.z); o.w = f2tf32(xv.w);
            *(uint4*)&Vs[r * 72 + c4 * 4] = o;
        }
        // P tile [128 i][128 j]: whole warp works one row at a time
#pragma unroll
        for (int v = 0; v < 16; v++) {
            int r = v * 8 + (tid >> 5);
            float cm = mi[r];
            float4 dv = *(const float4*)&g_invd[(size_t)(i0 + r) * S + jt + 4 * lane];
            float4 mv = *(const float4*)&mj[4 * lane];
            uint4 o;
            o.x = f2tf32(__expf(fminf(cm * mv.x * dv.x, 50.f)));
            o.y = f2tf32(__expf(fminf(cm * mv.y * dv.y, 50.f)));
            o.z = f2tf32(__expf(fminf(cm * mv.z * dv.z, 50.f)));
            o.w = f2tf32(__expf(fminf(cm * mv.w * dv.w, 50.f)));
            *(uint4*)&Ps[r * 128 + ((4 * lane) ^ ((r & 7) << 2))] = o;
        }
        __syncthreads();                             // tiles ready

#pragma unroll
        for (int ks = 0; ks < 16; ks++) {
            int k = ks * 8;
            uint32_t a[4];
            a[0] = Ps[(wm + g) * 128 + ((k + t) ^ swz)];
            a[1] = Ps[(wm + g + 8) * 128 + ((k + t) ^ swz)];
            a[2] = Ps[(wm + g) * 128 + ((k + t + 4) ^ swz)];
            a[3] = Ps[(wm + g + 8) * 128 + ((k + t + 4) ^ swz)];
#pragma unroll
            for (int nt = 0; nt < 8; nt++) {
                uint32_t bf[2];
                bf[0] = Vs[(k + t) * 72 + nt * 8 + g];
                bf[1] = Vs[(k + t + 4) * 72 + nt * 8 + g];
                mma_tf32(acc[nt], a, bf);
            }
            uint32_t ones[2] = {ONE, ONE};
            mma_tf32(sacc, a, ones);                 // rowsum accumulator
        }
    }

    float r0 = 1.0f / sacc[0];
    float r1 = 1.0f / sacc[2];
    size_t base0 = ((size_t)(b * S + i0 + wm + g)) * DM + h * HD;
    size_t base1 = base0 + (size_t)8 * DM;
#pragma unroll
    for (int nt = 0; nt < 8; nt++) {
        int c = nt * 8 + 2 * t;
        float2 v0, v1;
        v0.x = __uint_as_float(f2tf32(acc[nt][0] * r0));
        v0.y = __uint_as_float(f2tf32(acc[nt][1] * r0));
        v1.x = __uint_as_float(f2tf32(acc[nt][2] * r1));
        v1.y = __uint_as_float(f2tf32(acc[nt][3] * r1));
        *(float2*)&g_O[base0 + c] = v0;
        *(float2*)&g_O[base1 + c] = v1;
    }
}

// ---------------------------------------------------------------------------
// Kernel 4: Y = O @ Wc^T, tf32 tensor cores, cp.async double-buffered.
// 128x128 block tile, 8 warps, warp tile 64x32, K-chunk 32.
// Inputs already tf32-rounded (g_O by attn, g_Wc by wcvt).
// ---------------------------------------------------------------------------
__global__ __launch_bounds__(256, 2)
void out_gemm(float* __restrict__ Y) {
    extern __shared__ uint32_t sm_g[];
    uint32_t* As = sm_g;                 // [2][128][32] swizzled
    uint32_t* Bs = sm_g + 2 * 128 * 32;  // [2][128][32] swizzled

    int n0 = blockIdx.y * 128, j0 = blockIdx.x * 128;
    int tid = threadIdx.x;
    int w = tid >> 5, lane = tid & 31;
    int g = lane >> 2, t = lane & 3;
    int wm = (w >> 2) * 64, wn = (w & 3) * 32;
    int swz = g << 2;

    float acc[4][4][4] = {};

    // per-thread copy coordinates (4 float4 per array per chunk)
    int cr[4], cc[4];
#pragma unroll
    for (int v = 0; v < 4; v++) {
        int idx4 = v * 256 + tid;
        cr[v] = idx4 >> 3;
        cc[v] = (idx4 & 7) * 4;
    }

#define OG_ISSUE(buf, k0)                                                        \
    do {                                                                         \
        _Pragma("unroll")                                                        \
        for (int v = 0; v < 4; v++) {                                            \
            int r = cr[v], c = cc[v];                                            \
            int so = r * 32 + (c ^ ((r & 7) << 2));                              \
            uint32_t dA = (uint32_t)__cvta_generic_to_shared(&As[(buf)*4096 + so]); \
            const float* sA = &g_O[(size_t)(n0 + r) * DM + (k0) + c];            \
            asm volatile("cp.async.cg.shared.global [%0], [%1], 16;" ::"r"(dA), "l"(sA)); \
            uint32_t dB = (uint32_t)__cvta_generic_to_shared(&Bs[(buf)*4096 + so]); \
            const float* sB = &g_Wc[(size_t)(j0 + r) * DM + (k0) + c];           \
            asm volatile("cp.async.cg.shared.global [%0], [%1], 16;" ::"r"(dB), "l"(sB)); \
        }                                                                        \
        asm volatile("cp.async.commit_group;");                                  \
    } while (0)

    OG_ISSUE(0, 0);

    for (int ki = 0; ki < DM / 32; ki++) {
        asm volatile("cp.async.wait_group 0;");
        __syncthreads();
        if (ki + 1 < DM / 32) OG_ISSUE((ki + 1) & 1, (ki + 1) * 32);

        const uint32_t* Ab = &As[(ki & 1) * 4096];
        const uint32_t* Bb = &Bs[(ki & 1) * 4096];
#pragma unroll
        for (int ks = 0; ks < 4; ks++) {
            int k = ks * 8;
            uint32_t a[4][4], bf[4][2];
#pragma unroll
            for (int mt = 0; mt < 4; mt++) {
                int r = wm + mt * 16 + g;
                a[mt][0] = Ab[r * 32 + ((k + t) ^ swz)];
                a[mt][1] = Ab[(r + 8) * 32 + ((k + t) ^ swz)];
                a[mt][2] = Ab[r * 32 + ((k + t + 4) ^ swz)];
                a[mt][3] = Ab[(r + 8) * 32 + ((k + t + 4) ^ swz)];
            }
#pragma unroll
            for (int nt = 0; nt < 4; nt++) {
                int r = wn + nt * 8 + g;
                bf[nt][0] = Bb[r * 32 + ((k + t) ^ swz)];
                bf[nt][1] = Bb[r * 32 + ((k + t + 4) ^ swz)];
            }
#pragma unroll
            for (int mt = 0; mt < 4; mt++)
#pragma unroll
                for (int nt = 0; nt < 4; nt++)
                    mma_tf32(acc[mt][nt], a[mt], bf[nt]);
        }
    }
#pragma unroll
    for (int mt = 0; mt < 4; mt++) {
        int m = n0 + wm + mt * 16 + g;
#pragma unroll
        for (int nt = 0; nt < 4; nt++) {
            int j = j0 + wn + nt * 8 + 2 * t;
            float2 v0, v1;
            v0.x = acc[mt][nt][0]; v0.y = acc[mt][nt][1];
            v1.x = acc[mt][nt][2]; v1.y = acc[mt][nt][3];
            *(float2*)&Y[(size_t)m * DM + j] = v0;
            *(float2*)&Y[(size_t)(m + 8) * DM + j] = v1;
        }
    }
}

// ---------------------------------------------------------------------------
extern "C" void kernel_launch(void* const* d_in, const int* in_sizes, int n_in,
                              void* d_out, int out_size) {
    const float* x   = (const float*)d_in[0];   // [B,S,1024]
    const float* pos = (const float*)d_in[1];   // [S,64]
    const float* Wm  = (const float*)d_in[2];   // [16,64]
    const float* G   = (const float*)d_in[3];   // [16]
    const float* Wo  = (const float*)d_in[4];   // [1024,1024]
    float* out = (float*)d_out;                 // [B,S,1024]

    int S = in_sizes[1] / PDIM;
    int B = in_sizes[0] / (S * DM);

    static const int ATTN_SMEM = (128 * 128 + 128 * 72 + 256) * 4;
    static const int GEMM_SMEM = 4 * 128 * 32 * 4;
    cudaFuncSetAttribute(attn_kernel, cudaFuncAttributeMaxDynamicSharedMemorySize, ATTN_SMEM);
    cudaFuncSetAttribute(out_gemm, cudaFuncAttributeMaxDynamicSharedMemorySize, GEMM_SMEM);

    int nwarps = B * NHEADS * S;
    mass_kernel<<<nwarps / 8, 256>>>(x, Wm, G, S);

    wcvt_kernel<<<DM * DM / 1024, 256>>>(Wo);

    dim3 gd(S / 64, S / 64);
    dist_kernel<<<gd, 256>>>(pos, S);

    dim3 ga(S / 128, B * NHEADS);
    attn_kernel<<<ga, 256, ATTN_SMEM>>>(x, G, S);

    dim3 gg(DM / 128, (B * S) / 128);
    out_gemm<<<gg, 256, GEMM_SMEM>>>(out);
}